// round 9
// baseline (speedup 1.0000x reference)
#include <cuda_runtime.h>
#include <cstdint>

#define BN_SCALEF 0.9995003746877732f
#define LRELU(v) ((v) > 0.f ? (v) : 0.2f * (v))

typedef unsigned long long ull;

// ---------------- f32x2 packed helpers ----------------
__device__ __forceinline__ ull pack2same(float x) {
    ull r; asm("mov.b64 %0, {%1, %1};" : "=l"(r) : "f"(x)); return r;
}
__device__ __forceinline__ void ffma2(ull& d, ull a, ull b) {
    asm("fma.rn.f32x2 %0, %1, %2, %0;" : "+l"(d) : "l"(a), "l"(b));
}
__device__ __forceinline__ void unpack2(ull v, float& lo, float& hi) {
    asm("mov.b64 {%0, %1}, %2;" : "=f"(lo), "=f"(hi) : "l"(v));
}
__device__ __forceinline__ float getc(float4 v, int i) {
    switch (i) { case 0: return v.x; case 1: return v.y; case 2: return v.z; default: return v.w; }
}

// ---------------- scratch (device globals; no allocation) ----------------
__device__ __align__(16) float g_buf0[4 * 256 * 256 * 32];
__device__ __align__(16) float g_buf1[4 * 128 * 128 * 32];   // also ky-partial scratch
__device__ __align__(16) float g_buf2[4 * 64 * 64 * 32];
__device__ __align__(16) float g_buf3[4 * 64 * 64 * 32];
__device__ __align__(16) float g_disp[4 * 64 * 64 * 2];

// ------ layer 0: conv 3x3 (2->32) + BN + lrelu + pool; 2x2 tile x 16co ----
__global__ __launch_bounds__(128) void conv_pool_first(
    const float* __restrict__ fixedp, const float* __restrict__ movingp,
    float* __restrict__ out, const float* __restrict__ w)
{
    __shared__ __align__(16) float ws[9 * 2 * 32];
    for (int i = threadIdx.x; i < 576; i += blockDim.x) ws[i] = w[i];
    __syncthreads();

    const int H = 512, W = 512, Hp = 256, Wp = 256;
    int t = blockIdx.x * blockDim.x + threadIdx.x;
    int r = t & 1, q = t >> 1;
    int ox = q % Wp; int tmp = q / Wp; int oy = tmp % Hp; int b = tmp / Hp;
    int cy0 = oy * 2, cx0 = ox * 2;

    float xin[2][4][4];
    const float* fb = fixedp  + (size_t)b * H * W;
    const float* mb = movingp + (size_t)b * H * W;
#pragma unroll
    for (int dy = 0; dy < 4; dy++) {
        int iy = cy0 - 1 + dy;
        bool vy = (iy >= 0) && (iy < H);
#pragma unroll
        for (int dx = 0; dx < 4; dx++) {
            int ix = cx0 - 1 + dx;
            bool v = vy && (ix >= 0) && (ix < W);
            xin[0][dy][dx] = v ? __ldg(fb + (size_t)iy * W + ix) : 0.f;
            xin[1][dy][dx] = v ? __ldg(mb + (size_t)iy * W + ix) : 0.f;
        }
    }

    ull acc[2][2][8];
#pragma unroll
    for (int py = 0; py < 2; py++)
#pragma unroll
        for (int px = 0; px < 2; px++)
#pragma unroll
            for (int j = 0; j < 8; j++) acc[py][px][j] = 0ull;

#pragma unroll
    for (int ky = 0; ky < 3; ky++)
#pragma unroll
        for (int kx = 0; kx < 3; kx++)
#pragma unroll
            for (int ci = 0; ci < 2; ci++) {
                const ulonglong2* wp =
                    (const ulonglong2*)&ws[((ky * 3 + kx) * 2 + ci) * 32 + r * 16];
                ulonglong2 wa = wp[0], wb = wp[1], wc = wp[2], wd = wp[3];
#pragma unroll
                for (int py = 0; py < 2; py++)
#pragma unroll
                    for (int px = 0; px < 2; px++) {
                        ull x = pack2same(xin[ci][ky + py][kx + px]);
                        ffma2(acc[py][px][0], x, wa.x);
                        ffma2(acc[py][px][1], x, wa.y);
                        ffma2(acc[py][px][2], x, wb.x);
                        ffma2(acc[py][px][3], x, wb.y);
                        ffma2(acc[py][px][4], x, wc.x);
                        ffma2(acc[py][px][5], x, wc.y);
                        ffma2(acc[py][px][6], x, wd.x);
                        ffma2(acc[py][px][7], x, wd.y);
                    }
            }

    float* ob = out + ((size_t)(b * Hp + oy) * Wp + ox) * 32 + r * 16;
    float o[16];
#pragma unroll
    for (int j = 0; j < 8; j++) {
        float s0 = 0.f, s1 = 0.f;
#pragma unroll
        for (int py = 0; py < 2; py++)
#pragma unroll
            for (int px = 0; px < 2; px++) {
                float lo, hi; unpack2(acc[py][px][j], lo, hi);
                s0 += LRELU(lo * BN_SCALEF);
                s1 += LRELU(hi * BN_SCALEF);
            }
        o[2 * j] = 0.25f * s0; o[2 * j + 1] = 0.25f * s1;
    }
#pragma unroll
    for (int v4 = 0; v4 < 4; v4++)
        ((float4*)ob)[v4] = make_float4(o[4 * v4], o[4 * v4 + 1], o[4 * v4 + 2], o[4 * v4 + 3]);
}

// ------ conv 3x3 (32->32) + BN + lrelu + pool; software-pipelined ---------
struct ColBuf2 { float4 c[2][4]; };

template<int RS>
__global__ __launch_bounds__(128) void conv_pool32(
    const float* __restrict__ in, float* __restrict__ out,
    const float* __restrict__ w, int B, int H, int W)
{
    constexpr int CO = 32 / RS;
    constexpr int NP = CO / 2;

    __shared__ __align__(16) float ws[9216];
    for (int i = threadIdx.x; i < 2304; i += blockDim.x)
        ((float4*)ws)[i] = __ldg((const float4*)w + i);
    __syncthreads();

    int Hp = H >> 1, Wp = W >> 1;
    int t = blockIdx.x * blockDim.x + threadIdx.x;
    int r = t & (RS - 1), q = t / RS;
    int ox = q % Wp; int tmp = q / Wp; int oy = tmp % Hp; int b = tmp / Hp;
    int cy0 = oy * 2, cx0 = ox * 2;

    const float* inb = in + (size_t)b * H * W * 32;
    size_t rowstride = (size_t)W * 32;

    bool vc[4];
    const float* colp[4];
#pragma unroll
    for (int j = 0; j < 4; j++) {
        int ix = cx0 - 1 + j;
        vc[j] = (ix >= 0) && (ix < W);
        colp[j] = inb + (size_t)ix * 32;
    }

    auto load = [&](int it, ColBuf2& cb) {
        int ky = it >> 3, c4 = it & 7;
        int iy0 = cy0 + ky - 1;
        bool v0 = (iy0 >= 0) && (iy0 < H);
        bool v1 = (iy0 + 1 < H);
        size_t off0 = (size_t)iy0 * rowstride;
        size_t off1 = off0 + rowstride;
        const float4 z = make_float4(0.f, 0.f, 0.f, 0.f);
#pragma unroll
        for (int j = 0; j < 4; j++) {
            cb.c[0][j] = (v0 && vc[j]) ? __ldg((const float4*)(colp[j] + off0) + c4) : z;
            cb.c[1][j] = (v1 && vc[j]) ? __ldg((const float4*)(colp[j] + off1) + c4) : z;
        }
    };

    ull acc[2][2][NP];
#pragma unroll
    for (int py = 0; py < 2; py++)
#pragma unroll
        for (int px = 0; px < 2; px++)
#pragma unroll
            for (int j = 0; j < NP; j++) acc[py][px][j] = 0ull;

    auto compute = [&](int it, ColBuf2& cb) {
        int ky = it >> 3, c4 = it & 7;
        const float* wbase = &ws[(ky * 3) * 1024 + (c4 * 4) * 32 + r * CO];
#pragma unroll
        for (int ci = 0; ci < 4; ci++)
#pragma unroll
            for (int kx = 0; kx < 3; kx++) {
                const ulonglong2* wp = (const ulonglong2*)(wbase + kx * 1024 + ci * 32);
                ull wv[NP];
#pragma unroll
                for (int g = 0; g < NP / 2; g++) {
                    ulonglong2 z = wp[g];
                    wv[2 * g] = z.x; wv[2 * g + 1] = z.y;
                }
#pragma unroll
                for (int py = 0; py < 2; py++)
#pragma unroll
                    for (int px = 0; px < 2; px++) {
                        ull x = pack2same(getc(cb.c[py][kx + px], ci));
#pragma unroll
                        for (int j = 0; j < NP; j++) ffma2(acc[py][px][j], x, wv[j]);
                    }
            }
    };

    ColBuf2 bufA, bufB;
    load(0, bufA);
#pragma unroll 1
    for (int it = 0; it < 24; it += 2) {
        load(it + 1, bufB);
        compute(it, bufA);
        if (it + 2 < 24) load(it + 2, bufA);
        compute(it + 1, bufB);
    }

    float* ob = out + ((size_t)(b * Hp + oy) * Wp + ox) * 32 + r * CO;
    float o[CO];
#pragma unroll
    for (int j = 0; j < NP; j++) {
        float s0 = 0.f, s1 = 0.f;
#pragma unroll
        for (int py = 0; py < 2; py++)
#pragma unroll
            for (int px = 0; px < 2; px++) {
                float lo, hi; unpack2(acc[py][px][j], lo, hi);
                s0 += LRELU(lo * BN_SCALEF);
                s1 += LRELU(hi * BN_SCALEF);
            }
        o[2 * j] = 0.25f * s0; o[2 * j + 1] = 0.25f * s1;
    }
#pragma unroll
    for (int v4 = 0; v4 < CO / 4; v4++)
        ((float4*)ob)[v4] = make_float4(o[4 * v4], o[4 * v4 + 1], o[4 * v4 + 2], o[4 * v4 + 3]);
}

// ------ conv 3x3 (32->32) PARTIAL over one ky row; 2px x 8co, pipelined ---
// s = blockIdx.x>>8 selects ky row. Writes raw partial sums (no BN/lrelu).
struct ColBuf1 { float4 c[4]; };

__global__ __launch_bounds__(128) void conv32_part(
    const float* __restrict__ in, float* __restrict__ part,
    const float* __restrict__ w, int B, int H, int W)
{
    __shared__ __align__(16) float ws[9216];
    for (int i = threadIdx.x; i < 2304; i += blockDim.x)
        ((float4*)ws)[i] = __ldg((const float4*)w + i);
    __syncthreads();

    int s = blockIdx.x >> 8;                  // ky 0..2 (256 blocks each)
    int Wh = W >> 1;
    int t = (blockIdx.x & 255) * blockDim.x + threadIdx.x;
    int r = t & 3, q = t >> 2;
    int cxp = q % Wh; int tmp = q / Wh; int cy = tmp % H; int b = tmp / H;
    int cx0 = cxp * 2;

    const float* inb = in + (size_t)b * H * W * 32;
    size_t rowstride = (size_t)W * 32;

    int iy = cy + s - 1;
    bool vy = (iy >= 0) && (iy < H);

    bool vc[4];
    const float* colp[4];
#pragma unroll
    for (int j = 0; j < 4; j++) {
        int ix = cx0 - 1 + j;
        vc[j] = vy && (ix >= 0) && (ix < W);
        colp[j] = inb + (size_t)iy * rowstride + (size_t)ix * 32;
    }

    auto load = [&](int c4, ColBuf1& cb) {
        const float4 z = make_float4(0.f, 0.f, 0.f, 0.f);
#pragma unroll
        for (int j = 0; j < 4; j++)
            cb.c[j] = vc[j] ? __ldg((const float4*)colp[j] + c4) : z;
    };

    ull acc[2][4];
#pragma unroll
    for (int px = 0; px < 2; px++)
#pragma unroll
        for (int j = 0; j < 4; j++) acc[px][j] = 0ull;

    auto compute = [&](int c4, ColBuf1& cb) {
        const float* wbase = &ws[(s * 3) * 1024 + (c4 * 4) * 32 + r * 8];
#pragma unroll
        for (int ci = 0; ci < 4; ci++)
#pragma unroll
            for (int kx = 0; kx < 3; kx++) {
                const ulonglong2* wp = (const ulonglong2*)(wbase + kx * 1024 + ci * 32);
                ulonglong2 w01 = wp[0], w23 = wp[1];
#pragma unroll
                for (int px = 0; px < 2; px++) {
                    ull x = pack2same(getc(cb.c[kx + px], ci));
                    ffma2(acc[px][0], x, w01.x);
                    ffma2(acc[px][1], x, w01.y);
                    ffma2(acc[px][2], x, w23.x);
                    ffma2(acc[px][3], x, w23.y);
                }
            }
    };

    ColBuf1 bufA, bufB;
    load(0, bufA);
#pragma unroll 1
    for (int c4 = 0; c4 < 8; c4 += 2) {
        load(c4 + 1, bufB);
        compute(c4, bufA);
        if (c4 + 2 < 8) load(c4 + 2, bufA);
        compute(c4 + 1, bufB);
    }

    size_t pstride = (size_t)B * H * W * 32;
#pragma unroll
    for (int px = 0; px < 2; px++) {
        float* ob = part + s * pstride
                  + ((size_t)(b * H + cy) * W + (cx0 + px)) * 32 + r * 8;
        float o[8];
#pragma unroll
        for (int j = 0; j < 4; j++) unpack2(acc[px][j], o[2 * j], o[2 * j + 1]);
        ((float4*)ob)[0] = make_float4(o[0], o[1], o[2], o[3]);
        ((float4*)ob)[1] = make_float4(o[4], o[5], o[6], o[7]);
    }
}

// ------ combine 3 ky-partials + BN + lrelu --------------------------------
__global__ __launch_bounds__(256) void combine3(
    const float4* __restrict__ p, float4* __restrict__ out, int n4)
{
    int t = blockIdx.x * blockDim.x + threadIdx.x;
    if (t >= n4) return;
    float4 a = __ldg(p + t), b = __ldg(p + t + n4), c = __ldg(p + t + 2 * n4);
    float4 v;
    v.x = LRELU((a.x + b.x + c.x) * BN_SCALEF);
    v.y = LRELU((a.y + b.y + c.y) * BN_SCALEF);
    v.z = LRELU((a.z + b.z + c.z) * BN_SCALEF);
    v.w = LRELU((a.w + b.w + c.w) * BN_SCALEF);
    out[t] = v;
}

// ------- pointwise: pw0 (1x1, 32->32, lrelu, NO bn) + pw1 (32->2) --------
__global__ __launch_bounds__(128) void pointwise(
    const float* __restrict__ in, float* __restrict__ disp,
    const float* __restrict__ pw0, const float* __restrict__ pw1, int total)
{
    __shared__ float w0s[1024];
    __shared__ float w1s[64];
    for (int i = threadIdx.x; i < 1024; i += blockDim.x) w0s[i] = pw0[i];
    if (threadIdx.x < 64) w1s[threadIdx.x] = pw1[threadIdx.x];
    __syncthreads();

    int t = blockIdx.x * blockDim.x + threadIdx.x;
    if (t >= total) return;

    float x[32];
    const float4* ip = (const float4*)(in + (size_t)t * 32);
#pragma unroll
    for (int c4 = 0; c4 < 8; c4++) {
        float4 xv = __ldg(ip + c4);
        x[c4 * 4 + 0] = xv.x; x[c4 * 4 + 1] = xv.y;
        x[c4 * 4 + 2] = xv.z; x[c4 * 4 + 3] = xv.w;
    }
    float o0 = 0.f, o1 = 0.f;
#pragma unroll
    for (int co = 0; co < 32; co++) {
        float mid = 0.f;
#pragma unroll
        for (int ci = 0; ci < 32; ci++) mid = fmaf(x[ci], w0s[ci * 32 + co], mid);
        mid = LRELU(mid);
        o0 = fmaf(mid, w1s[co * 2 + 0], o0);
        o1 = fmaf(mid, w1s[co * 2 + 1], o1);
    }
    disp[(size_t)t * 2 + 0] = o0;
    disp[(size_t)t * 2 + 1] = o1;
}

// -------- B-spline upsample of disp (64x64 -> 512x512) + bilinear warp ---
__global__ __launch_bounds__(256) void bspline_warp(
    const float* __restrict__ disp, const float* __restrict__ movingp,
    float* __restrict__ out, int B, int H, int W)
{
    __shared__ float gd[4][7][2];

    int x = blockIdx.x * 32 + threadIdx.x;
    int y = blockIdx.y * 8 + threadIdx.y;
    int b = blockIdx.z;
    int jj = blockIdx.y;
    int ii0 = blockIdx.x * 4;

    {
        int tid = threadIdx.y * 32 + threadIdx.x;
        if (tid < 56) {
            int c = tid & 1, rest = tid >> 1;
            int col = rest % 7, row = rest / 7;
            int rj = jj - 1 + row, ri = ii0 - 1 + col;
            float v = 0.f;
            if (rj >= 0 && rj < 64 && ri >= 0 && ri < 64)
                v = __ldg(disp + (((size_t)b * 64 + rj) * 64 + ri) * 2 + c);
            gd[row][col][c] = v;
        }
    }
    __syncthreads();

    float xr = fminf((float)x * 0.125f, 63.f);
    float yr = fminf((float)y * 0.125f, 63.f);
    int ii = (int)floorf(xr);
    float u = xr * (1.f / 64.f), v = yr * (1.f / 64.f);

    float Bu[4], Bv[4];
    {
        float t2 = u * u, t3 = t2 * u;
        Bu[0] = -t3 + 3.f * t2 - 3.f * u + 1.f;
        Bu[1] = 3.f * t3 - 6.f * t2 + 4.f;
        Bu[2] = -3.f * t3 + 3.f * t2 + 3.f * u + 1.f;
        Bu[3] = t3;
    }
    {
        float t2 = v * v, t3 = t2 * v;
        Bv[0] = -t3 + 3.f * t2 - 3.f * v + 1.f;
        Bv[1] = 3.f * t3 - 6.f * t2 + 4.f;
        Bv[2] = -3.f * t3 + 3.f * t2 + 3.f * v + 1.f;
        Bv[3] = t3;
    }

    int ci = ii - ii0;
    float ic0 = 0.f, ic1 = 0.f;
#pragma unroll
    for (int m = 0; m < 4; m++) {
        float s0 = 0.f, s1 = 0.f;
#pragma unroll
        for (int n = 0; n < 4; n++) {
            s0 = fmaf(Bv[n], gd[m][ci + n][0], s0);
            s1 = fmaf(Bv[n], gd[m][ci + n][1], s1);
        }
        ic0 = fmaf(Bu[m], s0, ic0);
        ic1 = fmaf(Bu[m], s1, ic1);
    }

    float wx = ic0 + (float)x;
    float wy = ic1 + (float)y;

    float fx = floorf(wx), fy = floorf(wy);
    float x0 = fminf(fmaxf(fx, 0.f), (float)(W - 1));
    float x1 = fminf(fmaxf(fx + 1.f, 0.f), (float)(W - 1));
    float y0 = fminf(fmaxf(fy, 0.f), (float)(H - 1));
    float y1 = fminf(fmaxf(fy + 1.f, 0.f), (float)(H - 1));
    int x0i = (int)x0, x1i = (int)x1, y0i = (int)y0, y1i = (int)y1;

    const float* im = movingp + (size_t)b * H * W;
    float Q1 = __ldg(im + (size_t)y0i * W + x0i);
    float Q2 = __ldg(im + (size_t)y1i * W + x0i);
    float Q3 = __ldg(im + (size_t)y0i * W + x1i);
    float Q4 = __ldg(im + (size_t)y1i * W + x1i);

    const float eps = 1e-5f;
    float wxr = (x1 - wx) / (x1 - x0 + eps);
    float wxl = (wx - x0) / (x1 - x0 + eps);
    float R1 = wxr * Q1 + wxl * Q3;
    float R2 = wxr * Q2 + wxl * Q4;
    float o = (y1 - wy) / (y1 - y0 + eps) * R1 + (wy - y0) / (y1 - y0 + eps) * R2;

    out[(size_t)(b * H + y) * W + x] = o;
    float* grid = out + (size_t)B * H * W;
    grid[((size_t)(b * 2 + 0) * H + y) * W + x] = wx;
    grid[((size_t)(b * 2 + 1) * H + y) * W + x] = wy;
}

// --------------------------------- launch --------------------------------
extern "C" void kernel_launch(void* const* d_in, const int* in_sizes, int n_in,
                              void* d_out, int out_size)
{
    const float* fixedp  = (const float*)d_in[0];
    const float* movingp = (const float*)d_in[1];
    const float* w0  = (const float*)d_in[2];
    const float* w1  = (const float*)d_in[3];
    const float* w2  = (const float*)d_in[4];
    const float* fw0 = (const float*)d_in[5];
    const float* fw1 = (const float*)d_in[6];
    const float* pw0 = (const float*)d_in[7];
    const float* pw1 = (const float*)d_in[8];

    float *buf0, *buf1, *buf2, *buf3, *disp;
    cudaGetSymbolAddress((void**)&buf0, g_buf0);
    cudaGetSymbolAddress((void**)&buf1, g_buf1);
    cudaGetSymbolAddress((void**)&buf2, g_buf2);
    cudaGetSymbolAddress((void**)&buf3, g_buf3);
    cudaGetSymbolAddress((void**)&disp, g_disp);

    const int B = 4, H = 512, W = 512;
    const int fwN = B * 64 * 64 * 32;          // 524288 floats per fw image
    const int n4 = fwN / 4;

    conv_pool_first<<<(B * 256 * 256 * 2) / 128, 128>>>(fixedp, movingp, buf0, w0);
    conv_pool32<2><<<(B * 128 * 128 * 2) / 128, 128>>>(buf0, buf1, w1, B, 256, 256);
    conv_pool32<4><<<(B * 64 * 64 * 4) / 128, 128>>>(buf1, buf2, w2, B, 128, 128);

    // fw0: ky-split partials (into buf1 scratch) + combine -> buf3
    conv32_part<<<768, 128>>>(buf2, buf1, fw0, B, 64, 64);
    combine3<<<(n4 + 255) / 256, 256>>>((const float4*)buf1, (float4*)buf3, n4);
    // fw1: partials into buf1 + combine -> buf2
    conv32_part<<<768, 128>>>(buf3, buf1, fw1, B, 64, 64);
    combine3<<<(n4 + 255) / 256, 256>>>((const float4*)buf1, (float4*)buf2, n4);

    pointwise<<<(B * 64 * 64) / 128, 128>>>(buf2, disp, pw0, pw1, B * 64 * 64);
    dim3 bw_grid(16, 64, B), bw_block(32, 8);
    bspline_warp<<<bw_grid, bw_block>>>(disp, movingp, (float*)d_out, B, H, W);
}

// round 10
// speedup vs baseline: 1.0125x; 1.0125x over previous
#include <cuda_runtime.h>
#include <cstdint>

#define BN_SCALEF 0.9995003746877732f
#define LRELU(v) ((v) > 0.f ? (v) : 0.2f * (v))

typedef unsigned long long ull;

// ---------------- f32x2 packed helpers ----------------
__device__ __forceinline__ ull pack2same(float x) {
    ull r; asm("mov.b64 %0, {%1, %1};" : "=l"(r) : "f"(x)); return r;
}
__device__ __forceinline__ void ffma2(ull& d, ull a, ull b) {
    asm("fma.rn.f32x2 %0, %1, %2, %0;" : "+l"(d) : "l"(a), "l"(b));
}
__device__ __forceinline__ void unpack2(ull v, float& lo, float& hi) {
    asm("mov.b64 {%0, %1}, %2;" : "=f"(lo), "=f"(hi) : "l"(v));
}
__device__ __forceinline__ float getc(float4 v, int i) {
    switch (i) { case 0: return v.x; case 1: return v.y; case 2: return v.z; default: return v.w; }
}

// ---------------- scratch (device globals; no allocation) ----------------
__device__ __align__(16) float g_buf0[4 * 256 * 256 * 32];
__device__ __align__(16) float g_buf1[4 * 128 * 128 * 32];
__device__ __align__(16) float g_buf2[4 * 64 * 64 * 32];
__device__ __align__(16) float g_buf3[4 * 64 * 64 * 32];
__device__ __align__(16) float g_disp[4 * 64 * 64 * 2];

// ------ layer 0: conv 3x3 (2->32) + BN + lrelu + pool; 2x2 tile x 16co ----
__global__ __launch_bounds__(128) void conv_pool_first(
    const float* __restrict__ fixedp, const float* __restrict__ movingp,
    float* __restrict__ out, const float* __restrict__ w)
{
    __shared__ __align__(16) float ws[9 * 2 * 32];
    for (int i = threadIdx.x; i < 576; i += blockDim.x) ws[i] = w[i];
    __syncthreads();

    const int H = 512, W = 512, Hp = 256, Wp = 256;
    int t = blockIdx.x * blockDim.x + threadIdx.x;
    int r = t & 1, q = t >> 1;
    int ox = q % Wp; int tmp = q / Wp; int oy = tmp % Hp; int b = tmp / Hp;
    int cy0 = oy * 2, cx0 = ox * 2;

    float xin[2][4][4];
    const float* fb = fixedp  + (size_t)b * H * W;
    const float* mb = movingp + (size_t)b * H * W;
#pragma unroll
    for (int dy = 0; dy < 4; dy++) {
        int iy = cy0 - 1 + dy;
        bool vy = (iy >= 0) && (iy < H);
#pragma unroll
        for (int dx = 0; dx < 4; dx++) {
            int ix = cx0 - 1 + dx;
            bool v = vy && (ix >= 0) && (ix < W);
            xin[0][dy][dx] = v ? __ldg(fb + (size_t)iy * W + ix) : 0.f;
            xin[1][dy][dx] = v ? __ldg(mb + (size_t)iy * W + ix) : 0.f;
        }
    }

    ull acc[2][2][8];
#pragma unroll
    for (int py = 0; py < 2; py++)
#pragma unroll
        for (int px = 0; px < 2; px++)
#pragma unroll
            for (int j = 0; j < 8; j++) acc[py][px][j] = 0ull;

#pragma unroll
    for (int ky = 0; ky < 3; ky++)
#pragma unroll
        for (int kx = 0; kx < 3; kx++)
#pragma unroll
            for (int ci = 0; ci < 2; ci++) {
                const ulonglong2* wp =
                    (const ulonglong2*)&ws[((ky * 3 + kx) * 2 + ci) * 32 + r * 16];
                ulonglong2 wa = wp[0], wb = wp[1], wc = wp[2], wd = wp[3];
#pragma unroll
                for (int py = 0; py < 2; py++)
#pragma unroll
                    for (int px = 0; px < 2; px++) {
                        ull x = pack2same(xin[ci][ky + py][kx + px]);
                        ffma2(acc[py][px][0], x, wa.x);
                        ffma2(acc[py][px][1], x, wa.y);
                        ffma2(acc[py][px][2], x, wb.x);
                        ffma2(acc[py][px][3], x, wb.y);
                        ffma2(acc[py][px][4], x, wc.x);
                        ffma2(acc[py][px][5], x, wc.y);
                        ffma2(acc[py][px][6], x, wd.x);
                        ffma2(acc[py][px][7], x, wd.y);
                    }
            }

    float* ob = out + ((size_t)(b * Hp + oy) * Wp + ox) * 32 + r * 16;
    float o[16];
#pragma unroll
    for (int j = 0; j < 8; j++) {
        float s0 = 0.f, s1 = 0.f;
#pragma unroll
        for (int py = 0; py < 2; py++)
#pragma unroll
            for (int px = 0; px < 2; px++) {
                float lo, hi; unpack2(acc[py][px][j], lo, hi);
                s0 += LRELU(lo * BN_SCALEF);
                s1 += LRELU(hi * BN_SCALEF);
            }
        o[2 * j] = 0.25f * s0; o[2 * j + 1] = 0.25f * s1;
    }
#pragma unroll
    for (int v4 = 0; v4 < 4; v4++)
        ((float4*)ob)[v4] = make_float4(o[4 * v4], o[4 * v4 + 1], o[4 * v4 + 2], o[4 * v4 + 3]);
}

// ------ conv 3x3 (32->32) + BN + lrelu + pool; software-pipelined ---------
struct ColBuf2 { float4 c[2][4]; };

template<int RS>
__global__ __launch_bounds__(128) void conv_pool32(
    const float* __restrict__ in, float* __restrict__ out,
    const float* __restrict__ w, int B, int H, int W)
{
    constexpr int CO = 32 / RS;
    constexpr int NP = CO / 2;

    __shared__ __align__(16) float ws[9216];
    for (int i = threadIdx.x; i < 2304; i += blockDim.x)
        ((float4*)ws)[i] = __ldg((const float4*)w + i);
    __syncthreads();

    int Hp = H >> 1, Wp = W >> 1;
    int t = blockIdx.x * blockDim.x + threadIdx.x;
    int r = t & (RS - 1), q = t / RS;
    int ox = q % Wp; int tmp = q / Wp; int oy = tmp % Hp; int b = tmp / Hp;
    int cy0 = oy * 2, cx0 = ox * 2;

    const float* inb = in + (size_t)b * H * W * 32;
    size_t rowstride = (size_t)W * 32;

    bool vc[4];
    const float* colp[4];
#pragma unroll
    for (int j = 0; j < 4; j++) {
        int ix = cx0 - 1 + j;
        vc[j] = (ix >= 0) && (ix < W);
        colp[j] = inb + (size_t)ix * 32;
    }

    auto load = [&](int it, ColBuf2& cb) {
        int ky = it >> 3, c4 = it & 7;
        int iy0 = cy0 + ky - 1;
        bool v0 = (iy0 >= 0) && (iy0 < H);
        bool v1 = (iy0 + 1 < H);
        size_t off0 = (size_t)iy0 * rowstride;
        size_t off1 = off0 + rowstride;
        const float4 z = make_float4(0.f, 0.f, 0.f, 0.f);
#pragma unroll
        for (int j = 0; j < 4; j++) {
            cb.c[0][j] = (v0 && vc[j]) ? __ldg((const float4*)(colp[j] + off0) + c4) : z;
            cb.c[1][j] = (v1 && vc[j]) ? __ldg((const float4*)(colp[j] + off1) + c4) : z;
        }
    };

    ull acc[2][2][NP];
#pragma unroll
    for (int py = 0; py < 2; py++)
#pragma unroll
        for (int px = 0; px < 2; px++)
#pragma unroll
            for (int j = 0; j < NP; j++) acc[py][px][j] = 0ull;

    auto compute = [&](int it, ColBuf2& cb) {
        int ky = it >> 3, c4 = it & 7;
        const float* wbase = &ws[(ky * 3) * 1024 + (c4 * 4) * 32 + r * CO];
#pragma unroll
        for (int ci = 0; ci < 4; ci++)
#pragma unroll
            for (int kx = 0; kx < 3; kx++) {
                const ulonglong2* wp = (const ulonglong2*)(wbase + kx * 1024 + ci * 32);
                ull wv[NP];
#pragma unroll
                for (int g = 0; g < NP / 2; g++) {
                    ulonglong2 z = wp[g];
                    wv[2 * g] = z.x; wv[2 * g + 1] = z.y;
                }
#pragma unroll
                for (int py = 0; py < 2; py++)
#pragma unroll
                    for (int px = 0; px < 2; px++) {
                        ull x = pack2same(getc(cb.c[py][kx + px], ci));
#pragma unroll
                        for (int j = 0; j < NP; j++) ffma2(acc[py][px][j], x, wv[j]);
                    }
            }
    };

    ColBuf2 bufA, bufB;
    load(0, bufA);
#pragma unroll 1
    for (int it = 0; it < 24; it += 2) {
        load(it + 1, bufB);
        compute(it, bufA);
        if (it + 2 < 24) load(it + 2, bufA);
        compute(it + 1, bufB);
    }

    float* ob = out + ((size_t)(b * Hp + oy) * Wp + ox) * 32 + r * CO;
    float o[CO];
#pragma unroll
    for (int j = 0; j < NP; j++) {
        float s0 = 0.f, s1 = 0.f;
#pragma unroll
        for (int py = 0; py < 2; py++)
#pragma unroll
            for (int px = 0; px < 2; px++) {
                float lo, hi; unpack2(acc[py][px][j], lo, hi);
                s0 += LRELU(lo * BN_SCALEF);
                s1 += LRELU(hi * BN_SCALEF);
            }
        o[2 * j] = 0.25f * s0; o[2 * j + 1] = 0.25f * s1;
    }
#pragma unroll
    for (int v4 = 0; v4 < CO / 4; v4++)
        ((float4*)ob)[v4] = make_float4(o[4 * v4], o[4 * v4 + 1], o[4 * v4 + 2], o[4 * v4 + 3]);
}

// ------ conv 3x3 (32->32) + BN + lrelu (no pool); 2px x 8co, pipelined ----
struct ColBuf1 { float4 c[4]; };

__global__ __launch_bounds__(128) void conv32(
    const float* __restrict__ in, float* __restrict__ out,
    const float* __restrict__ w, int B, int H, int W)
{
    __shared__ __align__(16) float ws[9216];
    for (int i = threadIdx.x; i < 2304; i += blockDim.x)
        ((float4*)ws)[i] = __ldg((const float4*)w + i);
    __syncthreads();

    int Wh = W >> 1;
    int t = blockIdx.x * blockDim.x + threadIdx.x;
    int r = t & 3, q = t >> 2;
    int cxp = q % Wh; int tmp = q / Wh; int cy = tmp % H; int b = tmp / H;
    int cx0 = cxp * 2;

    const float* inb = in + (size_t)b * H * W * 32;
    size_t rowstride = (size_t)W * 32;

    bool vc[4];
    const float* colp[4];
#pragma unroll
    for (int j = 0; j < 4; j++) {
        int ix = cx0 - 1 + j;
        vc[j] = (ix >= 0) && (ix < W);
        colp[j] = inb + (size_t)ix * 32;
    }

    auto load = [&](int it, ColBuf1& cb) {
        int ky = it >> 3, c4 = it & 7;
        int iy = cy + ky - 1;
        bool vy = (iy >= 0) && (iy < H);
        size_t off = (size_t)iy * rowstride;
        const float4 z = make_float4(0.f, 0.f, 0.f, 0.f);
#pragma unroll
        for (int j = 0; j < 4; j++)
            cb.c[j] = (vy && vc[j]) ? __ldg((const float4*)(colp[j] + off) + c4) : z;
    };

    ull acc[2][4];
#pragma unroll
    for (int px = 0; px < 2; px++)
#pragma unroll
        for (int j = 0; j < 4; j++) acc[px][j] = 0ull;

    auto compute = [&](int it, ColBuf1& cb) {
        int ky = it >> 3, c4 = it & 7;
        const float* wbase = &ws[(ky * 3) * 1024 + (c4 * 4) * 32 + r * 8];
#pragma unroll
        for (int ci = 0; ci < 4; ci++)
#pragma unroll
            for (int kx = 0; kx < 3; kx++) {
                const ulonglong2* wp = (const ulonglong2*)(wbase + kx * 1024 + ci * 32);
                ulonglong2 w01 = wp[0], w23 = wp[1];
#pragma unroll
                for (int px = 0; px < 2; px++) {
                    ull x = pack2same(getc(cb.c[kx + px], ci));
                    ffma2(acc[px][0], x, w01.x);
                    ffma2(acc[px][1], x, w01.y);
                    ffma2(acc[px][2], x, w23.x);
                    ffma2(acc[px][3], x, w23.y);
                }
            }
    };

    ColBuf1 bufA, bufB;
    load(0, bufA);
#pragma unroll 1
    for (int it = 0; it < 24; it += 2) {
        load(it + 1, bufB);
        compute(it, bufA);
        if (it + 2 < 24) load(it + 2, bufA);
        compute(it + 1, bufB);
    }

#pragma unroll
    for (int px = 0; px < 2; px++) {
        float* ob = out + ((size_t)(b * H + cy) * W + (cx0 + px)) * 32 + r * 8;
        float o[8];
#pragma unroll
        for (int j = 0; j < 4; j++) {
            float lo, hi; unpack2(acc[px][j], lo, hi);
            o[2 * j] = LRELU(lo * BN_SCALEF);
            o[2 * j + 1] = LRELU(hi * BN_SCALEF);
        }
        ((float4*)ob)[0] = make_float4(o[0], o[1], o[2], o[3]);
        ((float4*)ob)[1] = make_float4(o[4], o[5], o[6], o[7]);
    }
}

// ------ fw1 conv + BN + lrelu FUSED with pw0 (lrelu) + pw1 -> disp --------
// Same conv structure as conv32; the 4 r-lanes of a pixel cooperate on the
// 1x1 convs via shfl butterflies. fw1 activations never touch gmem.
__global__ __launch_bounds__(128) void conv32_pw(
    const float* __restrict__ in, float* __restrict__ disp,
    const float* __restrict__ w, const float* __restrict__ pw0,
    const float* __restrict__ pw1, int B, int H, int W)
{
    __shared__ __align__(16) float ws[9216];
    __shared__ float w0t[1024];         // transposed pw0: [co][ci]
    __shared__ float w1s[64];
    for (int i = threadIdx.x; i < 2304; i += blockDim.x)
        ((float4*)ws)[i] = __ldg((const float4*)w + i);
    for (int i = threadIdx.x; i < 1024; i += blockDim.x)
        w0t[(i & 31) * 32 + (i >> 5)] = __ldg(pw0 + i);   // pw0[ci][co] -> w0t[co][ci]
    if (threadIdx.x < 64) w1s[threadIdx.x] = __ldg(pw1 + threadIdx.x);
    __syncthreads();

    int Wh = W >> 1;
    int t = blockIdx.x * blockDim.x + threadIdx.x;
    int r = t & 3, q = t >> 2;
    int cxp = q % Wh; int tmp = q / Wh; int cy = tmp % H; int b = tmp / H;
    int cx0 = cxp * 2;

    const float* inb = in + (size_t)b * H * W * 32;
    size_t rowstride = (size_t)W * 32;

    bool vc[4];
    const float* colp[4];
#pragma unroll
    for (int j = 0; j < 4; j++) {
        int ix = cx0 - 1 + j;
        vc[j] = (ix >= 0) && (ix < W);
        colp[j] = inb + (size_t)ix * 32;
    }

    auto load = [&](int it, ColBuf1& cb) {
        int ky = it >> 3, c4 = it & 7;
        int iy = cy + ky - 1;
        bool vy = (iy >= 0) && (iy < H);
        size_t off = (size_t)iy * rowstride;
        const float4 z = make_float4(0.f, 0.f, 0.f, 0.f);
#pragma unroll
        for (int j = 0; j < 4; j++)
            cb.c[j] = (vy && vc[j]) ? __ldg((const float4*)(colp[j] + off) + c4) : z;
    };

    ull acc[2][4];
#pragma unroll
    for (int px = 0; px < 2; px++)
#pragma unroll
        for (int j = 0; j < 4; j++) acc[px][j] = 0ull;

    auto compute = [&](int it, ColBuf1& cb) {
        int ky = it >> 3, c4 = it & 7;
        const float* wbase = &ws[(ky * 3) * 1024 + (c4 * 4) * 32 + r * 8];
#pragma unroll
        for (int ci = 0; ci < 4; ci++)
#pragma unroll
            for (int kx = 0; kx < 3; kx++) {
                const ulonglong2* wp = (const ulonglong2*)(wbase + kx * 1024 + ci * 32);
                ulonglong2 w01 = wp[0], w23 = wp[1];
#pragma unroll
                for (int px = 0; px < 2; px++) {
                    ull x = pack2same(getc(cb.c[kx + px], ci));
                    ffma2(acc[px][0], x, w01.x);
                    ffma2(acc[px][1], x, w01.y);
                    ffma2(acc[px][2], x, w23.x);
                    ffma2(acc[px][3], x, w23.y);
                }
            }
    };

    ColBuf1 bufA, bufB;
    load(0, bufA);
#pragma unroll 1
    for (int it = 0; it < 24; it += 2) {
        load(it + 1, bufB);
        compute(it, bufA);
        if (it + 2 < 24) load(it + 2, bufA);
        compute(it + 1, bufB);
    }

    // fw1 activations for this lane's 8 channels (ci = r*8 .. r*8+7 of pw0)
    float y[2][8];
#pragma unroll
    for (int px = 0; px < 2; px++)
#pragma unroll
        for (int j = 0; j < 4; j++) {
            float lo, hi; unpack2(acc[px][j], lo, hi);
            y[px][2 * j] = LRELU(lo * BN_SCALEF);
            y[px][2 * j + 1] = LRELU(hi * BN_SCALEF);
        }

    // pw0 (no BN, lrelu) + pw1: per co, lane partial over its 8 ci,
    // butterfly over the 4 r-lanes, lrelu, accumulate into (o0, o1).
    float o0[2] = {0.f, 0.f}, o1[2] = {0.f, 0.f};
#pragma unroll 1
    for (int co = 0; co < 32; co++) {
        const float4* wrow = (const float4*)&w0t[co * 32 + r * 8];
        float4 wa = wrow[0], wb = wrow[1];
        float w1a = w1s[co * 2], w1b = w1s[co * 2 + 1];
#pragma unroll
        for (int px = 0; px < 2; px++) {
            float p = 0.f;
            p = fmaf(y[px][0], wa.x, p);
            p = fmaf(y[px][1], wa.y, p);
            p = fmaf(y[px][2], wa.z, p);
            p = fmaf(y[px][3], wa.w, p);
            p = fmaf(y[px][4], wb.x, p);
            p = fmaf(y[px][5], wb.y, p);
            p = fmaf(y[px][6], wb.z, p);
            p = fmaf(y[px][7], wb.w, p);
            p += __shfl_xor_sync(0xffffffffu, p, 1);
            p += __shfl_xor_sync(0xffffffffu, p, 2);
            float m = LRELU(p);
            o0[px] = fmaf(m, w1a, o0[px]);
            o1[px] = fmaf(m, w1b, o1[px]);
        }
    }

    if (r == 0) {
#pragma unroll
        for (int px = 0; px < 2; px++) {
            size_t di = (((size_t)b * H + cy) * W + (cx0 + px)) * 2;
            disp[di + 0] = o0[px];
            disp[di + 1] = o1[px];
        }
    }
}

// -------- B-spline upsample of disp (64x64 -> 512x512) + bilinear warp ---
__global__ __launch_bounds__(256) void bspline_warp(
    const float* __restrict__ disp, const float* __restrict__ movingp,
    float* __restrict__ out, int B, int H, int W)
{
    __shared__ float gd[4][7][2];

    int x = blockIdx.x * 32 + threadIdx.x;
    int y = blockIdx.y * 8 + threadIdx.y;
    int b = blockIdx.z;
    int jj = blockIdx.y;
    int ii0 = blockIdx.x * 4;

    {
        int tid = threadIdx.y * 32 + threadIdx.x;
        if (tid < 56) {
            int c = tid & 1, rest = tid >> 1;
            int col = rest % 7, row = rest / 7;
            int rj = jj - 1 + row, ri = ii0 - 1 + col;
            float v = 0.f;
            if (rj >= 0 && rj < 64 && ri >= 0 && ri < 64)
                v = __ldg(disp + (((size_t)b * 64 + rj) * 64 + ri) * 2 + c);
            gd[row][col][c] = v;
        }
    }
    __syncthreads();

    float xr = fminf((float)x * 0.125f, 63.f);
    float yr = fminf((float)y * 0.125f, 63.f);
    int ii = (int)floorf(xr);
    float u = xr * (1.f / 64.f), v = yr * (1.f / 64.f);

    float Bu[4], Bv[4];
    {
        float t2 = u * u, t3 = t2 * u;
        Bu[0] = -t3 + 3.f * t2 - 3.f * u + 1.f;
        Bu[1] = 3.f * t3 - 6.f * t2 + 4.f;
        Bu[2] = -3.f * t3 + 3.f * t2 + 3.f * u + 1.f;
        Bu[3] = t3;
    }
    {
        float t2 = v * v, t3 = t2 * v;
        Bv[0] = -t3 + 3.f * t2 - 3.f * v + 1.f;
        Bv[1] = 3.f * t3 - 6.f * t2 + 4.f;
        Bv[2] = -3.f * t3 + 3.f * t2 + 3.f * v + 1.f;
        Bv[3] = t3;
    }

    int ci = ii - ii0;
    float ic0 = 0.f, ic1 = 0.f;
#pragma unroll
    for (int m = 0; m < 4; m++) {
        float s0 = 0.f, s1 = 0.f;
#pragma unroll
        for (int n = 0; n < 4; n++) {
            s0 = fmaf(Bv[n], gd[m][ci + n][0], s0);
            s1 = fmaf(Bv[n], gd[m][ci + n][1], s1);
        }
        ic0 = fmaf(Bu[m], s0, ic0);
        ic1 = fmaf(Bu[m], s1, ic1);
    }

    float wx = ic0 + (float)x;
    float wy = ic1 + (float)y;

    float fx = floorf(wx), fy = floorf(wy);
    float x0 = fminf(fmaxf(fx, 0.f), (float)(W - 1));
    float x1 = fminf(fmaxf(fx + 1.f, 0.f), (float)(W - 1));
    float y0 = fminf(fmaxf(fy, 0.f), (float)(H - 1));
    float y1 = fminf(fmaxf(fy + 1.f, 0.f), (float)(H - 1));
    int x0i = (int)x0, x1i = (int)x1, y0i = (int)y0, y1i = (int)y1;

    const float* im = movingp + (size_t)b * H * W;
    float Q1 = __ldg(im + (size_t)y0i * W + x0i);
    float Q2 = __ldg(im + (size_t)y1i * W + x0i);
    float Q3 = __ldg(im + (size_t)y0i * W + x1i);
    float Q4 = __ldg(im + (size_t)y1i * W + x1i);

    const float eps = 1e-5f;
    float wxr = (x1 - wx) / (x1 - x0 + eps);
    float wxl = (wx - x0) / (x1 - x0 + eps);
    float R1 = wxr * Q1 + wxl * Q3;
    float R2 = wxr * Q2 + wxl * Q4;
    float o = (y1 - wy) / (y1 - y0 + eps) * R1 + (wy - y0) / (y1 - y0 + eps) * R2;

    out[(size_t)(b * H + y) * W + x] = o;
    float* grid = out + (size_t)B * H * W;
    grid[((size_t)(b * 2 + 0) * H + y) * W + x] = wx;
    grid[((size_t)(b * 2 + 1) * H + y) * W + x] = wy;
}

// --------------------------------- launch --------------------------------
extern "C" void kernel_launch(void* const* d_in, const int* in_sizes, int n_in,
                              void* d_out, int out_size)
{
    const float* fixedp  = (const float*)d_in[0];
    const float* movingp = (const float*)d_in[1];
    const float* w0  = (const float*)d_in[2];
    const float* w1  = (const float*)d_in[3];
    const float* w2  = (const float*)d_in[4];
    const float* fw0 = (const float*)d_in[5];
    const float* fw1 = (const float*)d_in[6];
    const float* pw0 = (const float*)d_in[7];
    const float* pw1 = (const float*)d_in[8];

    float *buf0, *buf1, *buf2, *buf3, *disp;
    cudaGetSymbolAddress((void**)&buf0, g_buf0);
    cudaGetSymbolAddress((void**)&buf1, g_buf1);
    cudaGetSymbolAddress((void**)&buf2, g_buf2);
    cudaGetSymbolAddress((void**)&buf3, g_buf3);
    cudaGetSymbolAddress((void**)&disp, g_disp);

    const int B = 4, H = 512, W = 512;

    conv_pool_first<<<(B * 256 * 256 * 2) / 128, 128>>>(fixedp, movingp, buf0, w0);
    conv_pool32<2><<<(B * 128 * 128 * 2) / 128, 128>>>(buf0, buf1, w1, B, 256, 256);
    conv_pool32<4><<<(B * 64 * 64 * 4) / 128, 128>>>(buf1, buf2, w2, B, 128, 128);
    conv32<<<(B * 64 * 32 * 4) / 128, 128>>>(buf2, buf3, fw0, B, 64, 64);
    // fw1 + pw0 + pw1 fused -> disp
    conv32_pw<<<(B * 64 * 32 * 4) / 128, 128>>>(buf3, disp, fw1, pw0, pw1, B, 64, 64);
    dim3 bw_grid(16, 64, B), bw_block(32, 8);
    bspline_warp<<<bw_grid, bw_block>>>(disp, movingp, (float*)d_out, B, H, W);
}

// round 11
// speedup vs baseline: 1.0476x; 1.0347x over previous
#include <cuda_runtime.h>
#include <cstdint>

#define BN_SCALEF 0.9995003746877732f
#define LRELU(v) ((v) > 0.f ? (v) : 0.2f * (v))

typedef unsigned long long ull;

// ---------------- f32x2 packed helpers ----------------
__device__ __forceinline__ ull pack2same(float x) {
    ull r; asm("mov.b64 %0, {%1, %1};" : "=l"(r) : "f"(x)); return r;
}
__device__ __forceinline__ void ffma2(ull& d, ull a, ull b) {
    asm("fma.rn.f32x2 %0, %1, %2, %0;" : "+l"(d) : "l"(a), "l"(b));
}
__device__ __forceinline__ void unpack2(ull v, float& lo, float& hi) {
    asm("mov.b64 {%0, %1}, %2;" : "=f"(lo), "=f"(hi) : "l"(v));
}
__device__ __forceinline__ float getc(float4 v, int i) {
    switch (i) { case 0: return v.x; case 1: return v.y; case 2: return v.z; default: return v.w; }
}

// ---------------- scratch (device globals; no allocation) ----------------
__device__ __align__(16) float g_buf0[4 * 256 * 256 * 32];
__device__ __align__(16) float g_buf1[4 * 128 * 128 * 32];
__device__ __align__(16) float g_buf2[4 * 64 * 64 * 32];
__device__ __align__(16) float g_buf3[4 * 64 * 64 * 32];
__device__ __align__(16) float g_disp[4 * 64 * 64 * 2];

// ------ layer 0: conv 3x3 (2->32) + BN + lrelu + pool; 2x2 tile x 16co ----
__global__ __launch_bounds__(128) void conv_pool_first(
    const float* __restrict__ fixedp, const float* __restrict__ movingp,
    float* __restrict__ out, const float* __restrict__ w)
{
    __shared__ __align__(16) float ws[9 * 2 * 32];
    for (int i = threadIdx.x; i < 576; i += blockDim.x) ws[i] = w[i];
    __syncthreads();

    const int H = 512, W = 512, Hp = 256, Wp = 256;
    int t = blockIdx.x * blockDim.x + threadIdx.x;
    int r = t & 1, q = t >> 1;
    int ox = q % Wp; int tmp = q / Wp; int oy = tmp % Hp; int b = tmp / Hp;
    int cy0 = oy * 2, cx0 = ox * 2;

    float xin[2][4][4];
    const float* fb = fixedp  + (size_t)b * H * W;
    const float* mb = movingp + (size_t)b * H * W;
#pragma unroll
    for (int dy = 0; dy < 4; dy++) {
        int iy = cy0 - 1 + dy;
        bool vy = (iy >= 0) && (iy < H);
#pragma unroll
        for (int dx = 0; dx < 4; dx++) {
            int ix = cx0 - 1 + dx;
            bool v = vy && (ix >= 0) && (ix < W);
            xin[0][dy][dx] = v ? __ldg(fb + (size_t)iy * W + ix) : 0.f;
            xin[1][dy][dx] = v ? __ldg(mb + (size_t)iy * W + ix) : 0.f;
        }
    }

    ull acc[2][2][8];
#pragma unroll
    for (int py = 0; py < 2; py++)
#pragma unroll
        for (int px = 0; px < 2; px++)
#pragma unroll
            for (int j = 0; j < 8; j++) acc[py][px][j] = 0ull;

#pragma unroll
    for (int ky = 0; ky < 3; ky++)
#pragma unroll
        for (int kx = 0; kx < 3; kx++)
#pragma unroll
            for (int ci = 0; ci < 2; ci++) {
                const ulonglong2* wp =
                    (const ulonglong2*)&ws[((ky * 3 + kx) * 2 + ci) * 32 + r * 16];
                ulonglong2 wa = wp[0], wb = wp[1], wc = wp[2], wd = wp[3];
#pragma unroll
                for (int py = 0; py < 2; py++)
#pragma unroll
                    for (int px = 0; px < 2; px++) {
                        ull x = pack2same(xin[ci][ky + py][kx + px]);
                        ffma2(acc[py][px][0], x, wa.x);
                        ffma2(acc[py][px][1], x, wa.y);
                        ffma2(acc[py][px][2], x, wb.x);
                        ffma2(acc[py][px][3], x, wb.y);
                        ffma2(acc[py][px][4], x, wc.x);
                        ffma2(acc[py][px][5], x, wc.y);
                        ffma2(acc[py][px][6], x, wd.x);
                        ffma2(acc[py][px][7], x, wd.y);
                    }
            }

    float* ob = out + ((size_t)(b * Hp + oy) * Wp + ox) * 32 + r * 16;
    float o[16];
#pragma unroll
    for (int j = 0; j < 8; j++) {
        float s0 = 0.f, s1 = 0.f;
#pragma unroll
        for (int py = 0; py < 2; py++)
#pragma unroll
            for (int px = 0; px < 2; px++) {
                float lo, hi; unpack2(acc[py][px][j], lo, hi);
                s0 += LRELU(lo * BN_SCALEF);
                s1 += LRELU(hi * BN_SCALEF);
            }
        o[2 * j] = 0.25f * s0; o[2 * j + 1] = 0.25f * s1;
    }
#pragma unroll
    for (int v4 = 0; v4 < 4; v4++)
        ((float4*)ob)[v4] = make_float4(o[4 * v4], o[4 * v4 + 1], o[4 * v4 + 2], o[4 * v4 + 3]);
}

// ------ conv 3x3 (32->32) + BN + lrelu + pool; software-pipelined ---------
struct ColBuf2 { float4 c[2][4]; };

template<int RS>
__global__ __launch_bounds__(128) void conv_pool32(
    const float* __restrict__ in, float* __restrict__ out,
    const float* __restrict__ w, int B, int H, int W)
{
    constexpr int CO = 32 / RS;
    constexpr int NP = CO / 2;

    __shared__ __align__(16) float ws[9216];
    for (int i = threadIdx.x; i < 2304; i += blockDim.x)
        ((float4*)ws)[i] = __ldg((const float4*)w + i);
    __syncthreads();

    int Hp = H >> 1, Wp = W >> 1;
    int t = blockIdx.x * blockDim.x + threadIdx.x;
    int r = t & (RS - 1), q = t / RS;
    int ox = q % Wp; int tmp = q / Wp; int oy = tmp % Hp; int b = tmp / Hp;
    int cy0 = oy * 2, cx0 = ox * 2;

    const float* inb = in + (size_t)b * H * W * 32;
    size_t rowstride = (size_t)W * 32;

    bool vc[4];
    const float* colp[4];
#pragma unroll
    for (int j = 0; j < 4; j++) {
        int ix = cx0 - 1 + j;
        vc[j] = (ix >= 0) && (ix < W);
        colp[j] = inb + (size_t)ix * 32;
    }

    auto load = [&](int it, ColBuf2& cb) {
        int ky = it >> 3, c4 = it & 7;
        int iy0 = cy0 + ky - 1;
        bool v0 = (iy0 >= 0) && (iy0 < H);
        bool v1 = (iy0 + 1 < H);
        size_t off0 = (size_t)iy0 * rowstride;
        size_t off1 = off0 + rowstride;
        const float4 z = make_float4(0.f, 0.f, 0.f, 0.f);
#pragma unroll
        for (int j = 0; j < 4; j++) {
            cb.c[0][j] = (v0 && vc[j]) ? __ldg((const float4*)(colp[j] + off0) + c4) : z;
            cb.c[1][j] = (v1 && vc[j]) ? __ldg((const float4*)(colp[j] + off1) + c4) : z;
        }
    };

    ull acc[2][2][NP];
#pragma unroll
    for (int py = 0; py < 2; py++)
#pragma unroll
        for (int px = 0; px < 2; px++)
#pragma unroll
            for (int j = 0; j < NP; j++) acc[py][px][j] = 0ull;

    auto compute = [&](int it, ColBuf2& cb) {
        int ky = it >> 3, c4 = it & 7;
        const float* wbase = &ws[(ky * 3) * 1024 + (c4 * 4) * 32 + r * CO];
#pragma unroll
        for (int ci = 0; ci < 4; ci++)
#pragma unroll
            for (int kx = 0; kx < 3; kx++) {
                const ulonglong2* wp = (const ulonglong2*)(wbase + kx * 1024 + ci * 32);
                ull wv[NP];
#pragma unroll
                for (int g = 0; g < NP / 2; g++) {
                    ulonglong2 z = wp[g];
                    wv[2 * g] = z.x; wv[2 * g + 1] = z.y;
                }
#pragma unroll
                for (int py = 0; py < 2; py++)
#pragma unroll
                    for (int px = 0; px < 2; px++) {
                        ull x = pack2same(getc(cb.c[py][kx + px], ci));
#pragma unroll
                        for (int j = 0; j < NP; j++) ffma2(acc[py][px][j], x, wv[j]);
                    }
            }
    };

    ColBuf2 bufA, bufB;
    load(0, bufA);
#pragma unroll 1
    for (int it = 0; it < 24; it += 2) {
        load(it + 1, bufB);
        compute(it, bufA);
        if (it + 2 < 24) load(it + 2, bufA);
        compute(it + 1, bufB);
    }

    float* ob = out + ((size_t)(b * Hp + oy) * Wp + ox) * 32 + r * CO;
    float o[CO];
#pragma unroll
    for (int j = 0; j < NP; j++) {
        float s0 = 0.f, s1 = 0.f;
#pragma unroll
        for (int py = 0; py < 2; py++)
#pragma unroll
            for (int px = 0; px < 2; px++) {
                float lo, hi; unpack2(acc[py][px][j], lo, hi);
                s0 += LRELU(lo * BN_SCALEF);
                s1 += LRELU(hi * BN_SCALEF);
            }
        o[2 * j] = 0.25f * s0; o[2 * j + 1] = 0.25f * s1;
    }
#pragma unroll
    for (int v4 = 0; v4 < CO / 4; v4++)
        ((float4*)ob)[v4] = make_float4(o[4 * v4], o[4 * v4 + 1], o[4 * v4 + 2], o[4 * v4 + 3]);
}

// ------ conv 3x3 (32->32) + BN + lrelu (no pool); 2x2 tile x 8co ---------
// Same 8:1 FFMA2:LDS shape as conv_pool32, but writes all 4 conv pixels.
__global__ __launch_bounds__(128) void conv32_2x2(
    const float* __restrict__ in, float* __restrict__ out,
    const float* __restrict__ w, int B, int H, int W)
{
    __shared__ __align__(16) float ws[9216];
    for (int i = threadIdx.x; i < 2304; i += blockDim.x)
        ((float4*)ws)[i] = __ldg((const float4*)w + i);
    __syncthreads();

    int Hp = H >> 1, Wp = W >> 1;
    int t = blockIdx.x * blockDim.x + threadIdx.x;
    int r = t & 3, q = t >> 2;                       // r: co group of 8
    int ox = q % Wp; int tmp = q / Wp; int oy = tmp % Hp; int b = tmp / Hp;
    int cy0 = oy * 2, cx0 = ox * 2;

    const float* inb = in + (size_t)b * H * W * 32;
    size_t rowstride = (size_t)W * 32;

    bool vc[4];
    const float* colp[4];
#pragma unroll
    for (int j = 0; j < 4; j++) {
        int ix = cx0 - 1 + j;
        vc[j] = (ix >= 0) && (ix < W);
        colp[j] = inb + (size_t)ix * 32;
    }

    auto load = [&](int it, ColBuf2& cb) {
        int ky = it >> 3, c4 = it & 7;
        int iy0 = cy0 + ky - 1;
        bool v0 = (iy0 >= 0) && (iy0 < H);
        bool v1 = (iy0 + 1 < H);
        size_t off0 = (size_t)iy0 * rowstride;
        size_t off1 = off0 + rowstride;
        const float4 z = make_float4(0.f, 0.f, 0.f, 0.f);
#pragma unroll
        for (int j = 0; j < 4; j++) {
            cb.c[0][j] = (v0 && vc[j]) ? __ldg((const float4*)(colp[j] + off0) + c4) : z;
            cb.c[1][j] = (v1 && vc[j]) ? __ldg((const float4*)(colp[j] + off1) + c4) : z;
        }
    };

    ull acc[2][2][4];
#pragma unroll
    for (int py = 0; py < 2; py++)
#pragma unroll
        for (int px = 0; px < 2; px++)
#pragma unroll
            for (int j = 0; j < 4; j++) acc[py][px][j] = 0ull;

    auto compute = [&](int it, ColBuf2& cb) {
        int ky = it >> 3, c4 = it & 7;
        const float* wbase = &ws[(ky * 3) * 1024 + (c4 * 4) * 32 + r * 8];
#pragma unroll
        for (int ci = 0; ci < 4; ci++)
#pragma unroll
            for (int kx = 0; kx < 3; kx++) {
                const ulonglong2* wp = (const ulonglong2*)(wbase + kx * 1024 + ci * 32);
                ulonglong2 w01 = wp[0], w23 = wp[1];
#pragma unroll
                for (int py = 0; py < 2; py++)
#pragma unroll
                    for (int px = 0; px < 2; px++) {
                        ull x = pack2same(getc(cb.c[py][kx + px], ci));
                        ffma2(acc[py][px][0], x, w01.x);
                        ffma2(acc[py][px][1], x, w01.y);
                        ffma2(acc[py][px][2], x, w23.x);
                        ffma2(acc[py][px][3], x, w23.y);
                    }
            }
    };

    ColBuf2 bufA, bufB;
    load(0, bufA);
#pragma unroll 1
    for (int it = 0; it < 24; it += 2) {
        load(it + 1, bufB);
        compute(it, bufA);
        if (it + 2 < 24) load(it + 2, bufA);
        compute(it + 1, bufB);
    }

#pragma unroll
    for (int py = 0; py < 2; py++)
#pragma unroll
        for (int px = 0; px < 2; px++) {
            float* ob = out + ((size_t)(b * H + (cy0 + py)) * W + (cx0 + px)) * 32 + r * 8;
            float o[8];
#pragma unroll
            for (int j = 0; j < 4; j++) {
                float lo, hi; unpack2(acc[py][px][j], lo, hi);
                o[2 * j] = LRELU(lo * BN_SCALEF);
                o[2 * j + 1] = LRELU(hi * BN_SCALEF);
            }
            ((float4*)ob)[0] = make_float4(o[0], o[1], o[2], o[3]);
            ((float4*)ob)[1] = make_float4(o[4], o[5], o[6], o[7]);
        }
}

// ------ fw1 conv (2x2 tile x 8co) FUSED with pw0 (lrelu) + pw1 -> disp ----
__global__ __launch_bounds__(128) void conv32_pw(
    const float* __restrict__ in, float* __restrict__ disp,
    const float* __restrict__ w, const float* __restrict__ pw0,
    const float* __restrict__ pw1, int B, int H, int W)
{
    __shared__ __align__(16) float ws[9216];
    __shared__ float w0t[1024];         // transposed pw0: [co][ci]
    __shared__ float w1s[64];
    for (int i = threadIdx.x; i < 2304; i += blockDim.x)
        ((float4*)ws)[i] = __ldg((const float4*)w + i);
    for (int i = threadIdx.x; i < 1024; i += blockDim.x)
        w0t[(i & 31) * 32 + (i >> 5)] = __ldg(pw0 + i);
    if (threadIdx.x < 64) w1s[threadIdx.x] = __ldg(pw1 + threadIdx.x);
    __syncthreads();

    int Hp = H >> 1, Wp = W >> 1;
    int t = blockIdx.x * blockDim.x + threadIdx.x;
    int r = t & 3, q = t >> 2;
    int ox = q % Wp; int tmp = q / Wp; int oy = tmp % Hp; int b = tmp / Hp;
    int cy0 = oy * 2, cx0 = ox * 2;

    const float* inb = in + (size_t)b * H * W * 32;
    size_t rowstride = (size_t)W * 32;

    bool vc[4];
    const float* colp[4];
#pragma unroll
    for (int j = 0; j < 4; j++) {
        int ix = cx0 - 1 + j;
        vc[j] = (ix >= 0) && (ix < W);
        colp[j] = inb + (size_t)ix * 32;
    }

    auto load = [&](int it, ColBuf2& cb) {
        int ky = it >> 3, c4 = it & 7;
        int iy0 = cy0 + ky - 1;
        bool v0 = (iy0 >= 0) && (iy0 < H);
        bool v1 = (iy0 + 1 < H);
        size_t off0 = (size_t)iy0 * rowstride;
        size_t off1 = off0 + rowstride;
        const float4 z = make_float4(0.f, 0.f, 0.f, 0.f);
#pragma unroll
        for (int j = 0; j < 4; j++) {
            cb.c[0][j] = (v0 && vc[j]) ? __ldg((const float4*)(colp[j] + off0) + c4) : z;
            cb.c[1][j] = (v1 && vc[j]) ? __ldg((const float4*)(colp[j] + off1) + c4) : z;
        }
    };

    ull acc[2][2][4];
#pragma unroll
    for (int py = 0; py < 2; py++)
#pragma unroll
        for (int px = 0; px < 2; px++)
#pragma unroll
            for (int j = 0; j < 4; j++) acc[py][px][j] = 0ull;

    auto compute = [&](int it, ColBuf2& cb) {
        int ky = it >> 3, c4 = it & 7;
        const float* wbase = &ws[(ky * 3) * 1024 + (c4 * 4) * 32 + r * 8];
#pragma unroll
        for (int ci = 0; ci < 4; ci++)
#pragma unroll
            for (int kx = 0; kx < 3; kx++) {
                const ulonglong2* wp = (const ulonglong2*)(wbase + kx * 1024 + ci * 32);
                ulonglong2 w01 = wp[0], w23 = wp[1];
#pragma unroll
                for (int py = 0; py < 2; py++)
#pragma unroll
                    for (int px = 0; px < 2; px++) {
                        ull x = pack2same(getc(cb.c[py][kx + px], ci));
                        ffma2(acc[py][px][0], x, w01.x);
                        ffma2(acc[py][px][1], x, w01.y);
                        ffma2(acc[py][px][2], x, w23.x);
                        ffma2(acc[py][px][3], x, w23.y);
                    }
            }
    };

    ColBuf2 bufA, bufB;
    load(0, bufA);
#pragma unroll 1
    for (int it = 0; it < 24; it += 2) {
        load(it + 1, bufB);
        compute(it, bufA);
        if (it + 2 < 24) load(it + 2, bufA);
        compute(it + 1, bufB);
    }

    // fw1 activations (this lane's 8 channels) for 4 pixels
    float y[2][2][8];
#pragma unroll
    for (int py = 0; py < 2; py++)
#pragma unroll
        for (int px = 0; px < 2; px++)
#pragma unroll
            for (int j = 0; j < 4; j++) {
                float lo, hi; unpack2(acc[py][py == py ? px : px][j], lo, hi);
                lo = 0.f; hi = 0.f;   // (placeholder, overwritten below)
                (void)lo; (void)hi;
            }
#pragma unroll
    for (int py = 0; py < 2; py++)
#pragma unroll
        for (int px = 0; px < 2; px++)
#pragma unroll
            for (int j = 0; j < 4; j++) {
                float lo, hi; unpack2(acc[py][px][j], lo, hi);
                y[py][px][2 * j] = LRELU(lo * BN_SCALEF);
                y[py][px][2 * j + 1] = LRELU(hi * BN_SCALEF);
            }

    // pw0 (lrelu, no BN) + pw1 via 4-lane butterfly per pixel
    float o0[2][2] = {{0.f, 0.f}, {0.f, 0.f}};
    float o1[2][2] = {{0.f, 0.f}, {0.f, 0.f}};
#pragma unroll 1
    for (int co = 0; co < 32; co++) {
        const float4* wrow = (const float4*)&w0t[co * 32 + r * 8];
        float4 wa = wrow[0], wb = wrow[1];
        float w1a = w1s[co * 2], w1b = w1s[co * 2 + 1];
#pragma unroll
        for (int py = 0; py < 2; py++)
#pragma unroll
            for (int px = 0; px < 2; px++) {
                float p = 0.f;
                p = fmaf(y[py][px][0], wa.x, p);
                p = fmaf(y[py][px][1], wa.y, p);
                p = fmaf(y[py][px][2], wa.z, p);
                p = fmaf(y[py][px][3], wa.w, p);
                p = fmaf(y[py][px][4], wb.x, p);
                p = fmaf(y[py][px][5], wb.y, p);
                p = fmaf(y[py][px][6], wb.z, p);
                p = fmaf(y[py][px][7], wb.w, p);
                p += __shfl_xor_sync(0xffffffffu, p, 1);
                p += __shfl_xor_sync(0xffffffffu, p, 2);
                float m = LRELU(p);
                o0[py][px] = fmaf(m, w1a, o0[py][px]);
                o1[py][px] = fmaf(m, w1b, o1[py][px]);
            }
    }

    if (r == 0) {
#pragma unroll
        for (int py = 0; py < 2; py++)
#pragma unroll
            for (int px = 0; px < 2; px++) {
                size_t di = (((size_t)b * H + (cy0 + py)) * W + (cx0 + px)) * 2;
                disp[di + 0] = o0[py][px];
                disp[di + 1] = o1[py][px];
            }
    }
}

// -------- B-spline upsample of disp (64x64 -> 512x512) + bilinear warp ---
__global__ __launch_bounds__(256) void bspline_warp(
    const float* __restrict__ disp, const float* __restrict__ movingp,
    float* __restrict__ out, int B, int H, int W)
{
    __shared__ float gd[4][7][2];

    int x = blockIdx.x * 32 + threadIdx.x;
    int y = blockIdx.y * 8 + threadIdx.y;
    int b = blockIdx.z;
    int jj = blockIdx.y;
    int ii0 = blockIdx.x * 4;

    {
        int tid = threadIdx.y * 32 + threadIdx.x;
        if (tid < 56) {
            int c = tid & 1, rest = tid >> 1;
            int col = rest % 7, row = rest / 7;
            int rj = jj - 1 + row, ri = ii0 - 1 + col;
            float v = 0.f;
            if (rj >= 0 && rj < 64 && ri >= 0 && ri < 64)
                v = __ldg(disp + (((size_t)b * 64 + rj) * 64 + ri) * 2 + c);
            gd[row][col][c] = v;
        }
    }
    __syncthreads();

    float xr = fminf((float)x * 0.125f, 63.f);
    float yr = fminf((float)y * 0.125f, 63.f);
    int ii = (int)floorf(xr);
    float u = xr * (1.f / 64.f), v = yr * (1.f / 64.f);

    float Bu[4], Bv[4];
    {
        float t2 = u * u, t3 = t2 * u;
        Bu[0] = -t3 + 3.f * t2 - 3.f * u + 1.f;
        Bu[1] = 3.f * t3 - 6.f * t2 + 4.f;
        Bu[2] = -3.f * t3 + 3.f * t2 + 3.f * u + 1.f;
        Bu[3] = t3;
    }
    {
        float t2 = v * v, t3 = t2 * v;
        Bv[0] = -t3 + 3.f * t2 - 3.f * v + 1.f;
        Bv[1] = 3.f * t3 - 6.f * t2 + 4.f;
        Bv[2] = -3.f * t3 + 3.f * t2 + 3.f * v + 1.f;
        Bv[3] = t3;
    }

    int ci = ii - ii0;
    float ic0 = 0.f, ic1 = 0.f;
#pragma unroll
    for (int m = 0; m < 4; m++) {
        float s0 = 0.f, s1 = 0.f;
#pragma unroll
        for (int n = 0; n < 4; n++) {
            s0 = fmaf(Bv[n], gd[m][ci + n][0], s0);
            s1 = fmaf(Bv[n], gd[m][ci + n][1], s1);
        }
        ic0 = fmaf(Bu[m], s0, ic0);
        ic1 = fmaf(Bu[m], s1, ic1);
    }

    float wx = ic0 + (float)x;
    float wy = ic1 + (float)y;

    float fx = floorf(wx), fy = floorf(wy);
    float x0 = fminf(fmaxf(fx, 0.f), (float)(W - 1));
    float x1 = fminf(fmaxf(fx + 1.f, 0.f), (float)(W - 1));
    float y0 = fminf(fmaxf(fy, 0.f), (float)(H - 1));
    float y1 = fminf(fmaxf(fy + 1.f, 0.f), (float)(H - 1));
    int x0i = (int)x0, x1i = (int)x1, y0i = (int)y0, y1i = (int)y1;

    const float* im = movingp + (size_t)b * H * W;
    float Q1 = __ldg(im + (size_t)y0i * W + x0i);
    float Q2 = __ldg(im + (size_t)y1i * W + x0i);
    float Q3 = __ldg(im + (size_t)y0i * W + x1i);
    float Q4 = __ldg(im + (size_t)y1i * W + x1i);

    const float eps = 1e-5f;
    float wxr = (x1 - wx) / (x1 - x0 + eps);
    float wxl = (wx - x0) / (x1 - x0 + eps);
    float R1 = wxr * Q1 + wxl * Q3;
    float R2 = wxr * Q2 + wxl * Q4;
    float o = (y1 - wy) / (y1 - y0 + eps) * R1 + (wy - y0) / (y1 - y0 + eps) * R2;

    out[(size_t)(b * H + y) * W + x] = o;
    float* grid = out + (size_t)B * H * W;
    grid[((size_t)(b * 2 + 0) * H + y) * W + x] = wx;
    grid[((size_t)(b * 2 + 1) * H + y) * W + x] = wy;
}

// --------------------------------- launch --------------------------------
extern "C" void kernel_launch(void* const* d_in, const int* in_sizes, int n_in,
                              void* d_out, int out_size)
{
    const float* fixedp  = (const float*)d_in[0];
    const float* movingp = (const float*)d_in[1];
    const float* w0  = (const float*)d_in[2];
    const float* w1  = (const float*)d_in[3];
    const float* w2  = (const float*)d_in[4];
    const float* fw0 = (const float*)d_in[5];
    const float* fw1 = (const float*)d_in[6];
    const float* pw0 = (const float*)d_in[7];
    const float* pw1 = (const float*)d_in[8];

    float *buf0, *buf1, *buf2, *buf3, *disp;
    cudaGetSymbolAddress((void**)&buf0, g_buf0);
    cudaGetSymbolAddress((void**)&buf1, g_buf1);
    cudaGetSymbolAddress((void**)&buf2, g_buf2);
    cudaGetSymbolAddress((void**)&buf3, g_buf3);
    cudaGetSymbolAddress((void**)&disp, g_disp);

    const int B = 4, H = 512, W = 512;

    conv_pool_first<<<(B * 256 * 256 * 2) / 128, 128>>>(fixedp, movingp, buf0, w0);
    conv_pool32<2><<<(B * 128 * 128 * 2) / 128, 128>>>(buf0, buf1, w1, B, 256, 256);
    conv_pool32<4><<<(B * 64 * 64 * 4) / 128, 128>>>(buf1, buf2, w2, B, 128, 128);
    // fw0: 2x2 tile x 8co x 4 co-groups -> B*32*32*4 = 16384 threads, 128 blocks
    conv32_2x2<<<(B * 32 * 32 * 4) / 128, 128>>>(buf2, buf3, fw0, B, 64, 64);
    // fw1 + pw0 + pw1 fused -> disp (same shape)
    conv32_pw<<<(B * 32 * 32 * 4) / 128, 128>>>(buf3, disp, fw1, pw0, pw1, B, 64, 64);
    dim3 bw_grid(16, 64, B), bw_block(32, 8);
    bspline_warp<<<bw_grid, bw_block>>>(disp, movingp, (float*)d_out, B, H, W);
}